// round 12
// baseline (speedup 1.0000x reference)
#include <cuda_runtime.h>

#define NN 16384
#define CAP 96
#define SPAD 132

// Scratch (no allocations). Referenced ONLY from device code.
__device__ int   g_cnt[NN];
__device__ int   g_nbr[NN * CAP];
__device__ float g_z0[NN * 128];
__device__ float g_r0[NN * 128];
__device__ float g_z1[NN * 128];
__device__ float g_r1[NN * 128];
__device__ float g_z2[NN * 64];
__device__ float g_r2[NN * 64];
__device__ float g_h[NN * 128];

__device__ __forceinline__ float* zbuf(int s) { return s == 0 ? g_z0 : (s == 1 ? g_z1 : g_z2); }
__device__ __forceinline__ float* rbuf(int s) { return s == 0 ? g_r0 : (s == 1 ? g_r1 : g_r2); }

__global__ void zero_cnt_kernel() {
    int i = blockIdx.x * blockDim.x + threadIdx.x;
    if (i < NN) g_cnt[i] = 0;
}

// ---------------------------------------------------------------------------
// Scan one half-row stripe: block bb covers row bb, columns
// [q*8192, q*8192+8192) = 2048 contiguous float4 (32 KB) — identical DRAM
// access granularity to the R11 whole-matrix scan.
// ---------------------------------------------------------------------------
__device__ __forceinline__ void scan_stripe_block(const float* __restrict__ adj,
                                                  int q, int bb) {
    const float4* adj4 = reinterpret_cast<const float4*>(adj);
    size_t base = (size_t)bb * 4096 + q * 2048;
    int t = threadIdx.x;

    float4 v[8];
#pragma unroll
    for (int i = 0; i < 8; i++) v[i] = __ldcs(&adj4[base + t + i * 256]);

    int r = bb;
#pragma unroll
    for (int i = 0; i < 8; i++) {
        int c0 = q * 8192 + (t + i * 256) * 4;
        if (v[i].x != 0.0f) { int s = atomicAdd(&g_cnt[c0 + 0], 1); if (s < CAP) g_nbr[(c0 + 0) * CAP + s] = r; }
        if (v[i].y != 0.0f) { int s = atomicAdd(&g_cnt[c0 + 1], 1); if (s < CAP) g_nbr[(c0 + 1) * CAP + s] = r; }
        if (v[i].z != 0.0f) { int s = atomicAdd(&g_cnt[c0 + 2], 1); if (s < CAP) g_nbr[(c0 + 2) * CAP + s] = r; }
        if (v[i].w != 0.0f) { int s = atomicAdd(&g_cnt[c0 + 3], 1); if (s < CAP) g_nbr[(c0 + 3) * CAP + s] = r; }
    }
}

// ---------------------------------------------------------------------------
// LOW-REG GEMM block (layer 0, hidden under scan): 64x64 tile of
// x[N,128] @ [Wl0|Wr0]^T (fout=128). BK=32, 256 thr, TM=4xTN=4, ~42 regs.
// ---------------------------------------------------------------------------
__device__ __forceinline__ void gemm_block_small(
    const float* __restrict__ A,
    const float* __restrict__ Wl, const float* __restrict__ Wr,
    const float* __restrict__ bias, int rb, int cb,
    float (*As)[64], float (*Bs)[64])
{
    const int fout = 128;
    int tid = threadIdx.x;
    int rowBase = rb * 64;
    int vcol = cb * 64;

    const float* B;
    float* out;
    int colBase;
    bool addb;
    if (vcol < fout) { B = Wl; out = g_z0; colBase = vcol;        addb = false; }
    else             { B = Wr; out = g_r0; colBase = vcol - fout; addb = true;  }

    int tx = tid & 15;
    int ty = tid >> 4;

    float acc[4][4];
#pragma unroll
    for (int i = 0; i < 4; i++)
#pragma unroll
        for (int j = 0; j < 4; j++) acc[i][j] = 0.0f;

#pragma unroll 1
    for (int kt = 0; kt < 4; kt++) {
        int koff = kt * 32;
#pragma unroll
        for (int i = 0; i < 2; i++) {
            int lin = tid + i * 256;
            int m = lin >> 3;
            int kq = lin & 7;
            float4 v = *reinterpret_cast<const float4*>(
                &A[(size_t)(rowBase + m) * 128 + koff + kq * 4]);
            As[kq * 4 + 0][m] = v.x;
            As[kq * 4 + 1][m] = v.y;
            As[kq * 4 + 2][m] = v.z;
            As[kq * 4 + 3][m] = v.w;
        }
#pragma unroll
        for (int i = 0; i < 2; i++) {
            int lin = tid + i * 256;
            int o = lin >> 3;
            int kq = lin & 7;
            float4 v = *reinterpret_cast<const float4*>(
                &B[(size_t)(colBase + o) * 128 + koff + kq * 4]);
            Bs[kq * 4 + 0][o] = v.x;
            Bs[kq * 4 + 1][o] = v.y;
            Bs[kq * 4 + 2][o] = v.z;
            Bs[kq * 4 + 3][o] = v.w;
        }
        __syncthreads();

#pragma unroll
        for (int kk = 0; kk < 32; kk++) {
            float4 a0 = *reinterpret_cast<float4*>(&As[kk][ty * 4]);
            float4 b0 = *reinterpret_cast<float4*>(&Bs[kk][tx * 4]);
            float am[4] = {a0.x, a0.y, a0.z, a0.w};
            float bn[4] = {b0.x, b0.y, b0.z, b0.w};
#pragma unroll
            for (int i = 0; i < 4; i++)
#pragma unroll
                for (int j = 0; j < 4; j++)
                    acc[i][j] = fmaf(am[i], bn[j], acc[i][j]);
        }
        __syncthreads();
    }

#pragma unroll
    for (int i = 0; i < 4; i++) {
        int m = rowBase + ty * 4 + i;
        int o = colBase + tx * 4;
        float4 v;
        v.x = acc[i][0]; v.y = acc[i][1]; v.z = acc[i][2]; v.w = acc[i][3];
        if (addb) {
            float4 bv = *reinterpret_cast<const float4*>(&bias[o]);
            v.x += bv.x; v.y += bv.y; v.z += bv.z; v.w += bv.w;
        }
        *reinterpret_cast<float4*>(&out[(size_t)m * fout + o]) = v;
    }
}

__device__ __forceinline__ float4 f4add(float4 a, float4 b) {
    return make_float4(a.x + b.x, a.y + b.y, a.z + b.z, a.w + b.w);
}

// ---------------------------------------------------------------------------
// Gather (F=128, 256 threads, 8 targets/block), relu:
// g_h[t] = relu( mean_{n in nbr(t)} z[n] + r[t] )
// ---------------------------------------------------------------------------
__device__ __forceinline__ void gather128_block(int zsel, int t0) {
    int t = t0 + (threadIdx.x >> 5);
    int c = threadIdx.x & 31;

    int deg = min(g_cnt[t], CAP);
    const int* nb = &g_nbr[t * CAP];
    const float4* z4 = reinterpret_cast<const float4*>(zbuf(zsel));

    float4 s = make_float4(0.f, 0.f, 0.f, 0.f);
    int i = 0;
    for (; i + 4 <= deg; i += 4) {
        int4 nn = *reinterpret_cast<const int4*>(&nb[i]);
        float4 a = z4[(size_t)nn.x * 32 + c];
        float4 b = z4[(size_t)nn.y * 32 + c];
        float4 cc = z4[(size_t)nn.z * 32 + c];
        float4 d = z4[(size_t)nn.w * 32 + c];
        s = f4add(s, f4add(f4add(a, b), f4add(cc, d)));
    }
    for (; i < deg; i++)
        s = f4add(s, z4[(size_t)nb[i] * 32 + c]);

    float dinv = (deg > 0) ? (1.0f / (float)deg) : 0.0f;
    float4 rr = reinterpret_cast<const float4*>(rbuf(zsel))[(size_t)t * 32 + c];
    float4 o;
    o.x = fmaxf(s.x * dinv + rr.x, 0.f);
    o.y = fmaxf(s.y * dinv + rr.y, 0.f);
    o.z = fmaxf(s.z * dinv + rr.z, 0.f);
    o.w = fmaxf(s.w * dinv + rr.w, 0.f);
    reinterpret_cast<float4*>(g_h)[(size_t)t * 32 + c] = o;
}

// ---------------------------------------------------------------------------
// K2: gemm0 (1024 lean blocks) + scan stripe 0 (16384 blocks)
// ---------------------------------------------------------------------------
__global__ void __launch_bounds__(256) fusedA_kernel(
    const float* __restrict__ x, const float* __restrict__ adj,
    const float* __restrict__ Wl0, const float* __restrict__ Wr0,
    const float* __restrict__ b0)
{
    __shared__ float As[32][64];
    __shared__ float Bs[32][64];
    int bid = blockIdx.x;
    if (bid < 1024) {
        gemm_block_small(x, Wl0, Wr0, b0, bid >> 2, bid & 3, As, Bs);
        return;
    }
    scan_stripe_block(adj, 0, bid - 1024);
}

// ---------------------------------------------------------------------------
// K3: gather0 targets [0,8192) (1024 blocks) + scan stripe 1 (16384 blocks)
// (gather targets < 8192 need only cols [0,8192) = stripe 0, done in K2)
// ---------------------------------------------------------------------------
__global__ void __launch_bounds__(256) fusedB_kernel(const float* __restrict__ adj)
{
    int bid = blockIdx.x;
    if (bid < 1024) {
        gather128_block(0, bid * 8);
        return;
    }
    scan_stripe_block(adj, 1, bid - 1024);
}

// ---------------------------------------------------------------------------
// Fast double-buffered SGEMM block (BK=8, 128x128 tile, TM8xTN8,
// SINGLE sync per k-tile — the post-compute sync is redundant).
// A = g_h. Virtual B rows: o < fout -> Wl (-> z[zsel]), else Wr (-> r[zsel], +b).
// ---------------------------------------------------------------------------
__device__ __forceinline__ void fast_gemm_block(
    const float* __restrict__ Wl, const float* __restrict__ Wr,
    const float* __restrict__ bias, int fout, int zsel,
    int rowBase, int cbase,
    float (*As)[8][SPAD], float (*Bs)[8][SPAD])
{
    const float* A = g_h;
    int tid = threadIdx.x;
    int tx = tid & 15;
    int ty = tid >> 4;

    int lm = tid >> 1;
    int lkq = tid & 1;
    const float* aRow = &A[(size_t)(rowBase + lm) * 128 + lkq * 4];
    int ov = cbase + lm;
    const float* bRow = (ov < fout) ? &Wl[(size_t)ov * 128 + lkq * 4]
                                    : &Wr[(size_t)(ov - fout) * 128 + lkq * 4];

    float acc[8][8];
#pragma unroll
    for (int i = 0; i < 8; i++)
#pragma unroll
        for (int j = 0; j < 8; j++) acc[i][j] = 0.0f;

    float4 pa = *reinterpret_cast<const float4*>(aRow);
    float4 pb = *reinterpret_cast<const float4*>(bRow);
    As[0][lkq * 4 + 0][lm] = pa.x; As[0][lkq * 4 + 1][lm] = pa.y;
    As[0][lkq * 4 + 2][lm] = pa.z; As[0][lkq * 4 + 3][lm] = pa.w;
    Bs[0][lkq * 4 + 0][lm] = pb.x; Bs[0][lkq * 4 + 1][lm] = pb.y;
    Bs[0][lkq * 4 + 2][lm] = pb.z; Bs[0][lkq * 4 + 3][lm] = pb.w;
    __syncthreads();

#pragma unroll 1
    for (int kt = 0; kt < 16; kt++) {
        int buf = kt & 1;
        if (kt < 15) {
            pa = *reinterpret_cast<const float4*>(aRow + (kt + 1) * 8);
            pb = *reinterpret_cast<const float4*>(bRow + (kt + 1) * 8);
        }
#pragma unroll
        for (int kk = 0; kk < 8; kk++) {
            float4 a0 = *reinterpret_cast<float4*>(&As[buf][kk][ty * 4]);
            float4 a1 = *reinterpret_cast<float4*>(&As[buf][kk][64 + ty * 4]);
            float4 b0 = *reinterpret_cast<float4*>(&Bs[buf][kk][tx * 4]);
            float4 b1 = *reinterpret_cast<float4*>(&Bs[buf][kk][64 + tx * 4]);
            float am[8] = {a0.x, a0.y, a0.z, a0.w, a1.x, a1.y, a1.z, a1.w};
            float bn[8] = {b0.x, b0.y, b0.z, b0.w, b1.x, b1.y, b1.z, b1.w};
#pragma unroll
            for (int i = 0; i < 8; i++)
#pragma unroll
                for (int j = 0; j < 8; j++)
                    acc[i][j] = fmaf(am[i], bn[j], acc[i][j]);
        }
        if (kt < 15) {
            int nb = buf ^ 1;
            As[nb][lkq * 4 + 0][lm] = pa.x; As[nb][lkq * 4 + 1][lm] = pa.y;
            As[nb][lkq * 4 + 2][lm] = pa.z; As[nb][lkq * 4 + 3][lm] = pa.w;
            Bs[nb][lkq * 4 + 0][lm] = pb.x; Bs[nb][lkq * 4 + 1][lm] = pb.y;
            Bs[nb][lkq * 4 + 2][lm] = pb.z; Bs[nb][lkq * 4 + 3][lm] = pb.w;
            __syncthreads();
        }
    }

#pragma unroll
    for (int g = 0; g < 2; g++) {
        int ovc = cbase + g * 64 + tx * 4;
        bool isR = (ovc >= fout);
        int col = isR ? (ovc - fout) : ovc;
        float* dst = isR ? rbuf(zsel) : zbuf(zsel);
        float4 bv = make_float4(0.f, 0.f, 0.f, 0.f);
        if (isR) bv = *reinterpret_cast<const float4*>(&bias[col]);
#pragma unroll
        for (int h = 0; h < 2; h++) {
#pragma unroll
            for (int i = 0; i < 4; i++) {
                int m = rowBase + h * 64 + ty * 4 + i;
                float4 o;
                o.x = acc[h * 4 + i][g * 4 + 0] + bv.x;
                o.y = acc[h * 4 + i][g * 4 + 1] + bv.y;
                o.z = acc[h * 4 + i][g * 4 + 2] + bv.z;
                o.w = acc[h * 4 + i][g * 4 + 3] + bv.w;
                *reinterpret_cast<float4*>(&dst[(size_t)m * fout + col]) = o;
            }
        }
    }
}

// ---------------------------------------------------------------------------
// K4 (fat): gather0 targets [8192,16384) (1024 blocks, reads z0/r0, writes
// g_h rows 8192+) + gemm1 rows [0,8192) (128 blocks, reads g_h rows <8192
// from K3, writes z1/r1). No overlap between the two halves' accesses.
// ---------------------------------------------------------------------------
__global__ void __launch_bounds__(256, 2) fusedC_kernel(
    const float* __restrict__ Wl1, const float* __restrict__ Wr1,
    const float* __restrict__ b1)
{
    __shared__ float As[2][8][SPAD];
    __shared__ float Bs[2][8][SPAD];
    int bid = blockIdx.x;
    if (bid < 1024) {
        gather128_block(0, 8192 + bid * 8);
        return;
    }
    int gb = bid - 1024;                 // 0..127: 64 row-tiles x 2 col-tiles
    fast_gemm_block(Wl1, Wr1, b1, 128, 1, (gb >> 1) * 128, (gb & 1) * 128, As, Bs);
}

// Standalone fast gemm (K5: gemm1 rows 8192+; K7: gemm2).
__global__ void __launch_bounds__(256, 2) gemm_fast_kernel(
    const float* __restrict__ Wl, const float* __restrict__ Wr,
    const float* __restrict__ bias, int fout, int rowbase0, int zsel)
{
    __shared__ float As[2][8][SPAD];
    __shared__ float Bs[2][8][SPAD];
    fast_gemm_block(Wl, Wr, bias, fout, zsel,
                    rowbase0 + blockIdx.x * 128, blockIdx.y * 128, As, Bs);
}

// K6: gather1 full (reads z1/r1, writes g_h = h2)
__global__ void gather1_kernel() {
    gather128_block(1, blockIdx.x * 8);
}

// K8: final gather (F=64, no relu): out[t] = mean(z2[nbr]) + r2[t]
__global__ void gather64_kernel(float* __restrict__ out) {
    int t = blockIdx.x * 16 + (threadIdx.x >> 4);
    int c = threadIdx.x & 15;

    int deg = min(g_cnt[t], CAP);
    const int* nb = &g_nbr[t * CAP];
    const float4* z4 = reinterpret_cast<const float4*>(g_z2);

    float4 s = make_float4(0.f, 0.f, 0.f, 0.f);
    int i = 0;
    for (; i + 4 <= deg; i += 4) {
        int4 nn = *reinterpret_cast<const int4*>(&nb[i]);
        float4 a = z4[(size_t)nn.x * 16 + c];
        float4 b = z4[(size_t)nn.y * 16 + c];
        float4 cc = z4[(size_t)nn.z * 16 + c];
        float4 d = z4[(size_t)nn.w * 16 + c];
        s = f4add(s, f4add(f4add(a, b), f4add(cc, d)));
    }
    for (; i < deg; i++)
        s = f4add(s, z4[(size_t)nb[i] * 16 + c]);

    float dinv = (deg > 0) ? (1.0f / (float)deg) : 0.0f;
    float4 rr = reinterpret_cast<const float4*>(g_r2)[(size_t)t * 16 + c];
    float4 o;
    o.x = s.x * dinv + rr.x;
    o.y = s.y * dinv + rr.y;
    o.z = s.z * dinv + rr.z;
    o.w = s.w * dinv + rr.w;
    reinterpret_cast<float4*>(out)[(size_t)t * 16 + c] = o;
}

extern "C" void kernel_launch(void* const* d_in, const int* in_sizes, int n_in,
                              void* d_out, int out_size) {
    const float* x   = (const float*)d_in[0];
    const float* adj = (const float*)d_in[1];
    const float* Wl0 = (const float*)d_in[2];
    const float* b0  = (const float*)d_in[3];
    const float* Wr0 = (const float*)d_in[4];
    const float* Wl1 = (const float*)d_in[5];
    const float* b1  = (const float*)d_in[6];
    const float* Wr1 = (const float*)d_in[7];
    const float* Wl2 = (const float*)d_in[8];
    const float* b2  = (const float*)d_in[9];
    const float* Wr2 = (const float*)d_in[10];
    float* out = (float*)d_out;

    zero_cnt_kernel<<<NN / 256, 256>>>();

    // K2: layer-0 transform + scan column-stripe 0 (cols 0..8191)
    fusedA_kernel<<<1024 + 16384, 256>>>(x, adj, Wl0, Wr0, b0);

    // K3: scan stripe 1 (cols 8192..16383) + gather0 targets [0, 8192)
    fusedB_kernel<<<1024 + 16384, 256>>>(adj);

    // K4: gather0 targets [8192, 16384) + gemm1 rows [0, 8192)
    fusedC_kernel<<<1024 + 128, 256>>>(Wl1, Wr1, b1);

    // K5: gemm1 rows [8192, 16384)
    gemm_fast_kernel<<<dim3(64, 2), 256>>>(Wl1, Wr1, b1, 128, 8192, 1);

    // K6: gather1 full -> g_h (h2)
    gather1_kernel<<<2048, 256>>>();

    // K7: gemm2 (fout=64) -> z2/r2
    gemm_fast_kernel<<<dim3(128, 1), 256>>>(Wl2, Wr2, b2, 64, 0, 2);

    // K8: final gather -> d_out
    gather64_kernel<<<1024, 256>>>(out);
}